// round 10
// baseline (speedup 1.0000x reference)
#include <cuda_runtime.h>
#include <math.h>

// ---------------------------------------------------------------------------
// CoreLstm: 3-layer LayerNorm-LSTM.  T=32, B=256, H=384, 4H=1536, D_IN=1152
// R10 (= R2..R9 resubmitted; none ran — broker GPU acquisition timeouts):
//   fp32x2 packed-FMA GEMMs + persistent per-layer recurrence kernel with
//   manual grid barrier (96 CTAs, guaranteed co-resident on 148 SMs).
// ---------------------------------------------------------------------------

#define T_STEPS 32
#define BATCH   256
#define HIDDEN  384
#define G4      1536
#define DIN     1152
#define NROWS   (T_STEPS * BATCH)     // 8192
#define LN_EPS  1e-5f
#define RGRID   96                    // recurrence CTAs (<=148 -> co-resident)

#define OUT_OUTPUT 0
#define OUT_HN     (T_STEPS * BATCH * HIDDEN)
#define OUT_CN     (OUT_HN + 3 * BATCH * HIDDEN)

// Scratch (device globals: no allocation allowed)
__device__ float g_x0[NROWS * DIN];
__device__ float g_x [NROWS * HIDDEN];
__device__ float g_xg[NROWS * G4];
__device__ float g_hraw[BATCH * G4];
__device__ float g_h[BATCH * HIDDEN];
__device__ float g_c[BATCH * HIDDEN];
__device__ float g_stats[2][BATCH][2];     // per-step LN partial sums (dbl-buffered)
__device__ unsigned g_cnt;                  // grid barrier arrive counter
__device__ unsigned g_gen;                  // grid barrier generation (monotonic)

// ---------------------------------------------------------------------------
// packed fp32x2 helpers
// ---------------------------------------------------------------------------
__device__ __forceinline__ unsigned long long pack2(float lo, float hi) {
    unsigned long long r;
    asm("mov.b64 %0, {%1, %2};" : "=l"(r) : "f"(lo), "f"(hi));
    return r;
}
__device__ __forceinline__ float2 unpack2(unsigned long long v) {
    float2 f;
    asm("mov.b64 {%0, %1}, %2;" : "=f"(f.x), "=f"(f.y) : "l"(v));
    return f;
}
__device__ __forceinline__ void ffma2(unsigned long long& d,
                                      unsigned long long a,
                                      unsigned long long b) {
    asm("fma.rn.f32x2 %0, %1, %2, %0;" : "+l"(d) : "l"(a), "l"(b));
}

// ---------------------------------------------------------------------------
// concat [ent|spa|sca] -> x0 [8192, 1152]  (float4)
// ---------------------------------------------------------------------------
__global__ void concat_kernel(const float4* __restrict__ ent,
                              const float4* __restrict__ spa,
                              const float4* __restrict__ sca,
                              float4* __restrict__ x0) {
    const int total = NROWS * (DIN / 4);       // 8192 * 288
    for (int idx = blockIdx.x * blockDim.x + threadIdx.x; idx < total;
         idx += gridDim.x * blockDim.x) {
        int r = idx / 288;
        int c = idx - r * 288;
        float4 v;
        if (c < 64)        v = ent[r * 64 + c];
        else if (c < 128)  v = spa[r * 64 + (c - 64)];
        else               v = sca[r * 160 + (c - 128)];
        x0[idx] = v;
    }
}

// ---------------------------------------------------------------------------
// Big GEMM (fp32x2): C[M,N] = A[M,K] @ B[K,N].  BM=128, BN=64, BK=16,
// 256 threads, micro-tile 8x4 accumulated as 4 row-pairs x 4 cols (16 u64 acc).
// Requires M%128==0, N%64==0, K%16==0 (holds: M=8192, N=1536, K in {1152,384}).
// ---------------------------------------------------------------------------
__global__ void __launch_bounds__(256)
sgemm2_kernel(const float* __restrict__ A, const float* __restrict__ B,
              float* __restrict__ C, int M, int N, int K) {
    constexpr int BM = 128, BN = 64, BK = 16;
    __shared__ __align__(16) float As[BK][BM];
    __shared__ unsigned long long Bs[BK][BN];     // duplicated pairs (b,b)

    const int tid = threadIdx.x;
    const int ty = tid >> 4;      // 0..15 -> rows ty*8
    const int tx = tid & 15;      // 0..15 -> cols tx*4

    unsigned long long acc[4][4];
    #pragma unroll
    for (int p = 0; p < 4; p++)
        #pragma unroll
        for (int j = 0; j < 4; j++) acc[p][j] = 0ull;

    const int aRow = tid >> 1;            // 0..127
    const int aK   = (tid & 1) * 8;       // 0 or 8
    const int bRow = tid >> 4;            // 0..15
    const int bCol = (tid & 15) * 4;      // 0..60

    const float* Ab = A + (size_t)blockIdx.y * BM * K;
    const float* Bb = B + blockIdx.x * BN;

    for (int k0 = 0; k0 < K; k0 += BK) {
        float4 a0 = *reinterpret_cast<const float4*>(Ab + (size_t)aRow * K + k0 + aK);
        float4 a1 = *reinterpret_cast<const float4*>(Ab + (size_t)aRow * K + k0 + aK + 4);
        As[aK + 0][aRow] = a0.x; As[aK + 1][aRow] = a0.y;
        As[aK + 2][aRow] = a0.z; As[aK + 3][aRow] = a0.w;
        As[aK + 4][aRow] = a1.x; As[aK + 5][aRow] = a1.y;
        As[aK + 6][aRow] = a1.z; As[aK + 7][aRow] = a1.w;
        float4 b0 = *reinterpret_cast<const float4*>(Bb + (size_t)(k0 + bRow) * N + bCol);
        Bs[bRow][bCol + 0] = pack2(b0.x, b0.x);
        Bs[bRow][bCol + 1] = pack2(b0.y, b0.y);
        Bs[bRow][bCol + 2] = pack2(b0.z, b0.z);
        Bs[bRow][bCol + 3] = pack2(b0.w, b0.w);
        __syncthreads();

        #pragma unroll
        for (int kk = 0; kk < BK; kk++) {
            ulonglong2 ap0 = *reinterpret_cast<const ulonglong2*>(&As[kk][ty * 8]);
            ulonglong2 ap1 = *reinterpret_cast<const ulonglong2*>(&As[kk][ty * 8 + 4]);
            ulonglong2 bq0 = *reinterpret_cast<const ulonglong2*>(&Bs[kk][tx * 4]);
            ulonglong2 bq1 = *reinterpret_cast<const ulonglong2*>(&Bs[kk][tx * 4 + 2]);
            unsigned long long ar[4] = {ap0.x, ap0.y, ap1.x, ap1.y};
            unsigned long long br[4] = {bq0.x, bq0.y, bq1.x, bq1.y};
            #pragma unroll
            for (int p = 0; p < 4; p++)
                #pragma unroll
                for (int j = 0; j < 4; j++)
                    ffma2(acc[p][j], ar[p], br[j]);
        }
        __syncthreads();
    }

    const int row0 = blockIdx.y * BM + ty * 8;
    const int col0 = blockIdx.x * BN + tx * 4;
    #pragma unroll
    for (int p = 0; p < 4; p++) {
        float2 f0 = unpack2(acc[p][0]), f1 = unpack2(acc[p][1]);
        float2 f2 = unpack2(acc[p][2]), f3 = unpack2(acc[p][3]);
        *reinterpret_cast<float4*>(C + (size_t)(row0 + 2 * p) * N + col0) =
            make_float4(f0.x, f1.x, f2.x, f3.x);
        *reinterpret_cast<float4*>(C + (size_t)(row0 + 2 * p + 1) * N + col0) =
            make_float4(f0.y, f1.y, f2.y, f3.y);
    }
}

// ---------------------------------------------------------------------------
// Row LayerNorm over N=1536 in-place (for xg). one block per row, 256 thr.
// ---------------------------------------------------------------------------
__device__ __forceinline__ float2 block_sum2_8w(float s, float s2) {
    __shared__ float sh[16];
    const int lane = threadIdx.x & 31;
    const int wid  = threadIdx.x >> 5;
    #pragma unroll
    for (int o = 16; o > 0; o >>= 1) {
        s  += __shfl_down_sync(0xffffffffu, s, o);
        s2 += __shfl_down_sync(0xffffffffu, s2, o);
    }
    if (lane == 0) { sh[wid] = s; sh[8 + wid] = s2; }
    __syncthreads();
    if (wid == 0) {
        s  = (lane < 8) ? sh[lane] : 0.f;
        s2 = (lane < 8) ? sh[8 + lane] : 0.f;
        #pragma unroll
        for (int o = 4; o > 0; o >>= 1) {
            s  += __shfl_down_sync(0xffffffffu, s, o);
            s2 += __shfl_down_sync(0xffffffffu, s2, o);
        }
        if (lane == 0) { sh[0] = s; sh[8] = s2; }
    }
    __syncthreads();
    return make_float2(sh[0], sh[8]);
}

__global__ void __launch_bounds__(256)
ln_rows_kernel(float* __restrict__ X, const float* __restrict__ gam,
               const float* __restrict__ bet) {
    float* x = X + (size_t)blockIdx.x * G4;
    const int tid = threadIdx.x;
    float v[6];
    float s = 0.f, s2 = 0.f;
    #pragma unroll
    for (int q = 0; q < 6; q++) {
        v[q] = x[tid + q * 256];
        s += v[q];
        s2 = fmaf(v[q], v[q], s2);
    }
    float2 r2 = block_sum2_8w(s, s2);
    const float inv = 1.0f / (float)G4;
    float mu  = r2.x * inv;
    float var = fmaf(-mu, mu, r2.y * inv);
    float r   = rsqrtf(var + LN_EPS);
    #pragma unroll
    for (int q = 0; q < 6; q++) {
        int c = tid + q * 256;
        x[c] = fmaf((v[q] - mu) * r, gam[c], bet[c]);
    }
}

// ---------------------------------------------------------------------------
// Grid barrier (all RGRID CTAs co-resident). CG-style:
//   syncthreads -> [t0] fence, arrive, last resets cnt & bumps gen, others
//   spin on gen -> syncthreads.  Replay-idempotent: g_cnt ends at 0 every
//   barrier; g_gen is monotonic and re-read at kernel entry.
// ---------------------------------------------------------------------------
__device__ __forceinline__ void grid_barrier(unsigned& my_gen) {
    __syncthreads();
    if (threadIdx.x == 0) {
        __threadfence();
        my_gen += 1;
        unsigned a = atomicAdd(&g_cnt, 1u);
        if (a == RGRID - 1) {
            g_cnt = 0;
            __threadfence();
            atomicExch(&g_gen, my_gen);
        } else {
            while (*((volatile unsigned*)&g_gen) != my_gen) { __nanosleep(32); }
            __threadfence();
        }
    }
    __syncthreads();
}

// ---------------------------------------------------------------------------
// Persistent per-layer recurrence. 96 CTAs x 256 threads.
// Per step: phase A GEMM tile (32x128) of hraw = h @ wh + LN partial stats;
// barrier; phase B LN + gates + state update; barrier.
// ---------------------------------------------------------------------------
__global__ void __launch_bounds__(256)
lstm_layer_kernel(const float* __restrict__ xg,     // [T,B,1536] (already LN'd)
                  const float* __restrict__ wh,     // [384,1536]
                  const float* __restrict__ bias,
                  const float* __restrict__ ghw,
                  const float* __restrict__ ghb,
                  const float* __restrict__ h0,
                  const float* __restrict__ c0,
                  float* __restrict__ outbuf,       // [T,B,384]
                  float* __restrict__ hn,
                  float* __restrict__ cn) {
    constexpr int BM = 32, BN = 128, BK = 16;
    __shared__ __align__(16) float As[BK][BM];
    __shared__ unsigned long long Bs[BK][BN];

    const int tid = threadIdx.x;
    const int ty = tid >> 5;        // 0..7  -> rows ty*4
    const int tx = tid & 31;        // 0..31 -> cols tx*4
    const int blk = blockIdx.x;
    const int bm = blk / 12;        // 0..7  (row tile)
    const int bn = blk - bm * 12;   // 0..11 (col tile)
    const int u = blk * 256 + tid;  // 0..24575

    unsigned my_gen = 0;
    if (tid == 0) my_gen = *((volatile unsigned*)&g_gen);

    // phase 0: init h,c from h0,c0; zero stats
    #pragma unroll
    for (int w = 0; w < 4; w++) {
        int idx = u + w * 24576;
        g_h[idx] = h0[idx];
        g_c[idx] = c0[idx];
    }
    if (blk == 0) {
        g_stats[0][tid][0] = 0.f; g_stats[0][tid][1] = 0.f;
        g_stats[1][tid][0] = 0.f; g_stats[1][tid][1] = 0.f;
    }
    grid_barrier(my_gen);

    const int aRow = tid >> 3;            // 0..31
    const int aK   = (tid & 7) * 2;       // 0..14
    const int bRow = tid >> 4;            // 0..15
    const int bCol = (tid & 15) * 4;      // 0..60
    const float inv = 1.0f / (float)G4;

    for (int t = 0; t < T_STEPS; t++) {
        const int buf = t & 1;
        // ---- phase A: hraw tile = h @ wh ----
        unsigned long long acc[2][4];
        #pragma unroll
        for (int p = 0; p < 2; p++)
            #pragma unroll
            for (int j = 0; j < 4; j++) acc[p][j] = 0ull;

        for (int k0 = 0; k0 < HIDDEN; k0 += BK) {
            float2 av = *reinterpret_cast<const float2*>(
                g_h + (bm * BM + aRow) * HIDDEN + k0 + aK);
            As[aK][aRow]     = av.x;
            As[aK + 1][aRow] = av.y;
            const float* wr = wh + (size_t)(k0 + bRow) * G4 + bn * BN;
            float4 b0 = *reinterpret_cast<const float4*>(wr + bCol);
            float4 b1 = *reinterpret_cast<const float4*>(wr + bCol + 64);
            Bs[bRow][bCol + 0]  = pack2(b0.x, b0.x);
            Bs[bRow][bCol + 1]  = pack2(b0.y, b0.y);
            Bs[bRow][bCol + 2]  = pack2(b0.z, b0.z);
            Bs[bRow][bCol + 3]  = pack2(b0.w, b0.w);
            Bs[bRow][bCol + 64] = pack2(b1.x, b1.x);
            Bs[bRow][bCol + 65] = pack2(b1.y, b1.y);
            Bs[bRow][bCol + 66] = pack2(b1.z, b1.z);
            Bs[bRow][bCol + 67] = pack2(b1.w, b1.w);
            __syncthreads();

            #pragma unroll
            for (int kk = 0; kk < BK; kk++) {
                ulonglong2 ap  = *reinterpret_cast<const ulonglong2*>(&As[kk][ty * 4]);
                ulonglong2 bq0 = *reinterpret_cast<const ulonglong2*>(&Bs[kk][tx * 4]);
                ulonglong2 bq1 = *reinterpret_cast<const ulonglong2*>(&Bs[kk][tx * 4 + 2]);
                unsigned long long br[4] = {bq0.x, bq0.y, bq1.x, bq1.y};
                #pragma unroll
                for (int j = 0; j < 4; j++) ffma2(acc[0][j], ap.x, br[j]);
                #pragma unroll
                for (int j = 0; j < 4; j++) ffma2(acc[1][j], ap.y, br[j]);
            }
            __syncthreads();
        }

        // write hraw tile + per-row partial LN stats
        float rs[4], rq[4];
        #pragma unroll
        for (int p = 0; p < 2; p++) {
            float2 f0 = unpack2(acc[p][0]), f1 = unpack2(acc[p][1]);
            float2 f2 = unpack2(acc[p][2]), f3 = unpack2(acc[p][3]);
            int rlo = bm * BM + ty * 4 + 2 * p;
            float4 vlo = make_float4(f0.x, f1.x, f2.x, f3.x);
            float4 vhi = make_float4(f0.y, f1.y, f2.y, f3.y);
            *reinterpret_cast<float4*>(g_hraw + (size_t)rlo * G4 + bn * BN + tx * 4) = vlo;
            *reinterpret_cast<float4*>(g_hraw + (size_t)(rlo + 1) * G4 + bn * BN + tx * 4) = vhi;
            rs[2 * p]     = vlo.x + vlo.y + vlo.z + vlo.w;
            rq[2 * p]     = vlo.x * vlo.x + vlo.y * vlo.y + vlo.z * vlo.z + vlo.w * vlo.w;
            rs[2 * p + 1] = vhi.x + vhi.y + vhi.z + vhi.w;
            rq[2 * p + 1] = vhi.x * vhi.x + vhi.y * vhi.y + vhi.z * vhi.z + vhi.w * vhi.w;
        }
        #pragma unroll
        for (int o = 16; o > 0; o >>= 1) {
            #pragma unroll
            for (int r = 0; r < 4; r++) {
                rs[r] += __shfl_down_sync(0xffffffffu, rs[r], o);
                rq[r] += __shfl_down_sync(0xffffffffu, rq[r], o);
            }
        }
        if (tx == 0) {
            int rbase = bm * BM + ty * 4;
            #pragma unroll
            for (int r = 0; r < 4; r++) {
                atomicAdd(&g_stats[buf][rbase + r][0], rs[r]);
                atomicAdd(&g_stats[buf][rbase + r][1], rq[r]);
            }
        }
        grid_barrier(my_gen);

        // ---- phase B: LN + gates + state update ----
        const float* xgt = xg + (size_t)t * BATCH * G4;
        #pragma unroll
        for (int w = 0; w < 4; w++) {
            int idx = u + w * 24576;
            int b = idx / HIDDEN;
            int i = idx - b * HIDDEN;
            float s  = g_stats[buf][b][0];
            float s2 = g_stats[buf][b][1];
            float mu  = s * inv;
            float var = fmaf(-mu, mu, s2 * inv);
            float r   = rsqrtf(var + LN_EPS);
            float gate[4];
            #pragma unroll
            for (int q = 0; q < 4; q++) {
                int col = i + q * HIDDEN;
                float v = g_hraw[(size_t)b * G4 + col];
                float lnv = fmaf((v - mu) * r, ghw[col], ghb[col]);
                gate[q] = xgt[(size_t)b * G4 + col] + lnv + bias[col];
            }
            float ig = 1.f / (1.f + expf(-gate[0]));
            float fg = 1.f / (1.f + expf(-gate[1]));
            float og = 1.f / (1.f + expf(-gate[2]));
            float ug = tanhf(gate[3]);
            float cv = fmaf(fg, g_c[idx], ig * ug);
            float hv = og * tanhf(cv);
            g_c[idx] = cv;
            g_h[idx] = hv;
            outbuf[(size_t)t * BATCH * HIDDEN + idx] = hv;
            if (t == T_STEPS - 1) { hn[idx] = hv; cn[idx] = cv; }
        }
        // zero next step's stats buffer
        if (blk == 0) {
            int nb = buf ^ 1;
            g_stats[nb][tid][0] = 0.f;
            g_stats[nb][tid][1] = 0.f;
        }
        grid_barrier(my_gen);
    }
}

// ---------------------------------------------------------------------------
extern "C" void kernel_launch(void* const* d_in, const int* in_sizes, int n_in,
                              void* d_out, int out_size) {
    const float* ent  = (const float*)d_in[0];
    const float* spa  = (const float*)d_in[1];
    const float* sca  = (const float*)d_in[2];
    const float* h0   = (const float*)d_in[3];
    const float* c0   = (const float*)d_in[4];
    const float* wx0  = (const float*)d_in[5];
    const float* wx1  = (const float*)d_in[6];
    const float* wx2  = (const float*)d_in[7];
    const float* wh   = (const float*)d_in[8];
    const float* bias = (const float*)d_in[9];
    const float* gxw  = (const float*)d_in[10];
    const float* gxb  = (const float*)d_in[11];
    const float* ghw  = (const float*)d_in[12];
    const float* ghb  = (const float*)d_in[13];
    float* out = (float*)d_out;

    float *x0, *x, *xg;
    cudaGetSymbolAddress((void**)&x0, g_x0);
    cudaGetSymbolAddress((void**)&x,  g_x);
    cudaGetSymbolAddress((void**)&xg, g_xg);

    concat_kernel<<<512, 256>>>((const float4*)ent, (const float4*)spa,
                                (const float4*)sca, (float4*)x0);

    const float* wx_l[3] = {wx0, wx1, wx2};
    const int    K_l[3]  = {DIN, HIDDEN, HIDDEN};
    const int BH = BATCH * HIDDEN;

    for (int l = 0; l < 3; l++) {
        const float* A = (l == 0) ? x0 : x;
        dim3 g1(G4 / 64, NROWS / 128);
        sgemm2_kernel<<<g1, 256>>>(A, wx_l[l], xg, NROWS, G4, K_l[l]);
        ln_rows_kernel<<<NROWS, 256>>>(xg, gxw + l * G4, gxb + l * G4);

        float* outbuf = (l == 2) ? (out + OUT_OUTPUT) : x;
        lstm_layer_kernel<<<RGRID, 256>>>(
            xg, wh + (size_t)l * HIDDEN * G4,
            bias + l * G4, ghw + l * G4, ghb + l * G4,
            h0 + l * BH, c0 + l * BH,
            outbuf, out + OUT_HN + l * BH, out + OUT_CN + l * BH);
    }
}

// round 11
// speedup vs baseline: 1.2389x; 1.2389x over previous
#include <cuda_runtime.h>
#include <math.h>

// ---------------------------------------------------------------------------
// CoreLstm: 3-layer LayerNorm-LSTM.  T=32, B=256, H=384, 4H=1536, D_IN=1152
// R11: REVERT persistent recurrence (R10: 6578us, occ 12.5%, fma 8.4% — grid
//      barriers + 1 CTA/SM starved the machine). Back to R1's launch-based
//      structure (4009us measured), keeping fp32x2 packed-FMA GEMMs.
// ---------------------------------------------------------------------------

#define T_STEPS 32
#define BATCH   256
#define HIDDEN  384
#define G4      1536
#define DIN     1152
#define NROWS   (T_STEPS * BATCH)     // 8192
#define LN_EPS  1e-5f

#define OUT_OUTPUT 0
#define OUT_HN     (T_STEPS * BATCH * HIDDEN)
#define OUT_CN     (OUT_HN + 3 * BATCH * HIDDEN)

// Scratch (device globals: no allocation allowed)
__device__ float g_x0[NROWS * DIN];
__device__ float g_x [NROWS * HIDDEN];
__device__ float g_xg[NROWS * G4];
__device__ float g_hraw[BATCH * G4];
__device__ float g_h[BATCH * HIDDEN];
__device__ float g_c[BATCH * HIDDEN];

// ---------------------------------------------------------------------------
// packed fp32x2 helpers
// ---------------------------------------------------------------------------
__device__ __forceinline__ unsigned long long pack2(float lo, float hi) {
    unsigned long long r;
    asm("mov.b64 %0, {%1, %2};" : "=l"(r) : "f"(lo), "f"(hi));
    return r;
}
__device__ __forceinline__ float2 unpack2(unsigned long long v) {
    float2 f;
    asm("mov.b64 {%0, %1}, %2;" : "=f"(f.x), "=f"(f.y) : "l"(v));
    return f;
}
__device__ __forceinline__ void ffma2(unsigned long long& d,
                                      unsigned long long a,
                                      unsigned long long b) {
    asm("fma.rn.f32x2 %0, %1, %2, %0;" : "+l"(d) : "l"(a), "l"(b));
}

// ---------------------------------------------------------------------------
// concat [ent|spa|sca] -> x0 [8192, 1152]  (float4)
// ---------------------------------------------------------------------------
__global__ void concat_kernel(const float4* __restrict__ ent,
                              const float4* __restrict__ spa,
                              const float4* __restrict__ sca,
                              float4* __restrict__ x0) {
    const int total = NROWS * (DIN / 4);       // 8192 * 288
    for (int idx = blockIdx.x * blockDim.x + threadIdx.x; idx < total;
         idx += gridDim.x * blockDim.x) {
        int r = idx / 288;
        int c = idx - r * 288;
        float4 v;
        if (c < 64)        v = ent[r * 64 + c];
        else if (c < 128)  v = spa[r * 64 + (c - 64)];
        else               v = sca[r * 160 + (c - 128)];
        x0[idx] = v;
    }
}

// ---------------------------------------------------------------------------
// Big GEMM (fp32x2): C[M,N] = A[M,K] @ B[K,N].  BM=128, BN=64, BK=16,
// 256 threads, micro-tile 8x4 as 4 row-pairs x 4 cols (16 u64 acc).
// Requires M%128==0, N%64==0, K%16==0 (M=8192, N=1536, K in {1152,384}).
// ---------------------------------------------------------------------------
__global__ void __launch_bounds__(256)
sgemm2_kernel(const float* __restrict__ A, const float* __restrict__ B,
              float* __restrict__ C, int M, int N, int K) {
    constexpr int BM = 128, BN = 64, BK = 16;
    __shared__ __align__(16) float As[BK][BM];
    __shared__ unsigned long long Bs[BK][BN];     // duplicated pairs (b,b)

    const int tid = threadIdx.x;
    const int ty = tid >> 4;      // 0..15 -> rows ty*8
    const int tx = tid & 15;      // 0..15 -> cols tx*4

    unsigned long long acc[4][4];
    #pragma unroll
    for (int p = 0; p < 4; p++)
        #pragma unroll
        for (int j = 0; j < 4; j++) acc[p][j] = 0ull;

    const int aRow = tid >> 1;            // 0..127
    const int aK   = (tid & 1) * 8;       // 0 or 8
    const int bRow = tid >> 4;            // 0..15
    const int bCol = (tid & 15) * 4;      // 0..60

    const float* Ab = A + (size_t)blockIdx.y * BM * K;
    const float* Bb = B + blockIdx.x * BN;

    for (int k0 = 0; k0 < K; k0 += BK) {
        float4 a0 = *reinterpret_cast<const float4*>(Ab + (size_t)aRow * K + k0 + aK);
        float4 a1 = *reinterpret_cast<const float4*>(Ab + (size_t)aRow * K + k0 + aK + 4);
        As[aK + 0][aRow] = a0.x; As[aK + 1][aRow] = a0.y;
        As[aK + 2][aRow] = a0.z; As[aK + 3][aRow] = a0.w;
        As[aK + 4][aRow] = a1.x; As[aK + 5][aRow] = a1.y;
        As[aK + 6][aRow] = a1.z; As[aK + 7][aRow] = a1.w;
        float4 b0 = *reinterpret_cast<const float4*>(Bb + (size_t)(k0 + bRow) * N + bCol);
        Bs[bRow][bCol + 0] = pack2(b0.x, b0.x);
        Bs[bRow][bCol + 1] = pack2(b0.y, b0.y);
        Bs[bRow][bCol + 2] = pack2(b0.z, b0.z);
        Bs[bRow][bCol + 3] = pack2(b0.w, b0.w);
        __syncthreads();

        #pragma unroll
        for (int kk = 0; kk < BK; kk++) {
            ulonglong2 ap0 = *reinterpret_cast<const ulonglong2*>(&As[kk][ty * 8]);
            ulonglong2 ap1 = *reinterpret_cast<const ulonglong2*>(&As[kk][ty * 8 + 4]);
            ulonglong2 bq0 = *reinterpret_cast<const ulonglong2*>(&Bs[kk][tx * 4]);
            ulonglong2 bq1 = *reinterpret_cast<const ulonglong2*>(&Bs[kk][tx * 4 + 2]);
            unsigned long long ar[4] = {ap0.x, ap0.y, ap1.x, ap1.y};
            unsigned long long br[4] = {bq0.x, bq0.y, bq1.x, bq1.y};
            #pragma unroll
            for (int p = 0; p < 4; p++)
                #pragma unroll
                for (int j = 0; j < 4; j++)
                    ffma2(acc[p][j], ar[p], br[j]);
        }
        __syncthreads();
    }

    const int row0 = blockIdx.y * BM + ty * 8;
    const int col0 = blockIdx.x * BN + tx * 4;
    #pragma unroll
    for (int p = 0; p < 4; p++) {
        float2 f0 = unpack2(acc[p][0]), f1 = unpack2(acc[p][1]);
        float2 f2 = unpack2(acc[p][2]), f3 = unpack2(acc[p][3]);
        *reinterpret_cast<float4*>(C + (size_t)(row0 + 2 * p) * N + col0) =
            make_float4(f0.x, f1.x, f2.x, f3.x);
        *reinterpret_cast<float4*>(C + (size_t)(row0 + 2 * p + 1) * N + col0) =
            make_float4(f0.y, f1.y, f2.y, f3.y);
    }
}

// ---------------------------------------------------------------------------
// Small GEMM (fp32x2) for recurrence: C[256,1536] = h[256,384] @ wh[384,1536].
// BM=32, BN=64, BK=16, 256 threads, micro-tile 4x2 (2 row-pairs x 2 cols).
// grid (N/64=24, M/32=8) = 192 CTAs -> healthy multi-CTA occupancy.
// ---------------------------------------------------------------------------
__global__ void __launch_bounds__(256)
sgemm2s_kernel(const float* __restrict__ A, const float* __restrict__ B,
               float* __restrict__ C) {
    constexpr int BM = 32, BN = 64, BK = 16, K = HIDDEN, N = G4;
    __shared__ __align__(16) float As[BK][BM];
    __shared__ unsigned long long Bs[BK][BN];

    const int tid = threadIdx.x;
    const int ty = tid >> 5;      // 0..7  -> rows ty*4
    const int tx = tid & 31;      // 0..31 -> cols tx*2

    unsigned long long acc[2][2];
    acc[0][0] = acc[0][1] = acc[1][0] = acc[1][1] = 0ull;

    const int aRow = tid >> 3;            // 0..31
    const int aK   = (tid & 7) * 2;       // 0..14
    const int bRow = tid >> 4;            // 0..15
    const int bCol = (tid & 15) * 4;      // 0..60

    const float* Ab = A + (size_t)blockIdx.y * BM * K;
    const float* Bb = B + blockIdx.x * BN;

    for (int k0 = 0; k0 < K; k0 += BK) {
        float2 av = *reinterpret_cast<const float2*>(Ab + (size_t)aRow * K + k0 + aK);
        As[aK][aRow]     = av.x;
        As[aK + 1][aRow] = av.y;
        float4 b0 = *reinterpret_cast<const float4*>(Bb + (size_t)(k0 + bRow) * N + bCol);
        Bs[bRow][bCol + 0] = pack2(b0.x, b0.x);
        Bs[bRow][bCol + 1] = pack2(b0.y, b0.y);
        Bs[bRow][bCol + 2] = pack2(b0.z, b0.z);
        Bs[bRow][bCol + 3] = pack2(b0.w, b0.w);
        __syncthreads();

        #pragma unroll
        for (int kk = 0; kk < BK; kk++) {
            ulonglong2 ap = *reinterpret_cast<const ulonglong2*>(&As[kk][ty * 4]);
            ulonglong2 bq = *reinterpret_cast<const ulonglong2*>(&Bs[kk][tx * 2]);
            ffma2(acc[0][0], ap.x, bq.x);
            ffma2(acc[0][1], ap.x, bq.y);
            ffma2(acc[1][0], ap.y, bq.x);
            ffma2(acc[1][1], ap.y, bq.y);
        }
        __syncthreads();
    }

    const int row0 = blockIdx.y * BM + ty * 4;
    const int col0 = blockIdx.x * BN + tx * 2;
    #pragma unroll
    for (int p = 0; p < 2; p++) {
        float2 f0 = unpack2(acc[p][0]), f1 = unpack2(acc[p][1]);
        *reinterpret_cast<float2*>(C + (size_t)(row0 + 2 * p) * G4 + col0) =
            make_float2(f0.x, f1.x);
        *reinterpret_cast<float2*>(C + (size_t)(row0 + 2 * p + 1) * G4 + col0) =
            make_float2(f0.y, f1.y);
    }
}

// ---------------------------------------------------------------------------
// block-wide sum of (s, s2) for NW warps
// ---------------------------------------------------------------------------
template<int NW>
__device__ __forceinline__ float2 block_sum2(float s, float s2) {
    __shared__ float sh[2 * NW];
    const int lane = threadIdx.x & 31;
    const int wid  = threadIdx.x >> 5;
    #pragma unroll
    for (int o = 16; o > 0; o >>= 1) {
        s  += __shfl_down_sync(0xffffffffu, s, o);
        s2 += __shfl_down_sync(0xffffffffu, s2, o);
    }
    if (lane == 0) { sh[wid] = s; sh[NW + wid] = s2; }
    __syncthreads();
    if (wid == 0) {
        s  = (lane < NW) ? sh[lane] : 0.f;
        s2 = (lane < NW) ? sh[NW + lane] : 0.f;
        #pragma unroll
        for (int o = 16; o > 0; o >>= 1) {
            s  += __shfl_down_sync(0xffffffffu, s, o);
            s2 += __shfl_down_sync(0xffffffffu, s2, o);
        }
        if (lane == 0) { sh[0] = s; sh[NW] = s2; }
    }
    __syncthreads();
    return make_float2(sh[0], sh[NW]);
}

// ---------------------------------------------------------------------------
// In-place row LayerNorm over N=1536 (for xg). one block per row, 256 thr.
// ---------------------------------------------------------------------------
__global__ void __launch_bounds__(256)
ln_rows_kernel(float* __restrict__ X, const float* __restrict__ gam,
               const float* __restrict__ bet) {
    float* x = X + (size_t)blockIdx.x * G4;
    const int tid = threadIdx.x;
    float v[6];
    float s = 0.f, s2 = 0.f;
    #pragma unroll
    for (int q = 0; q < 6; q++) {
        v[q] = x[tid + q * 256];
        s += v[q];
        s2 = fmaf(v[q], v[q], s2);
    }
    float2 r2 = block_sum2<8>(s, s2);
    const float inv = 1.0f / (float)G4;
    float mu  = r2.x * inv;
    float var = fmaf(-mu, mu, r2.y * inv);
    float r   = rsqrtf(var + LN_EPS);
    #pragma unroll
    for (int q = 0; q < 6; q++) {
        int c = tid + q * 256;
        x[c] = fmaf((v[q] - mu) * r, gam[c], bet[c]);
    }
}

// ---------------------------------------------------------------------------
// One LSTM timestep: LN(hraw) + gates + state update.
// one block per batch row (256 blocks), 384 threads (thread = hid index)
// ---------------------------------------------------------------------------
__global__ void lstm_step_kernel(const float* __restrict__ hraw,   // [256,1536]
                                 const float* __restrict__ xg_t,   // [256,1536]
                                 const float* __restrict__ bias,   // [1536]
                                 const float* __restrict__ ghw,    // [1536]
                                 const float* __restrict__ ghb,    // [1536]
                                 float* __restrict__ h,            // [256,384]
                                 float* __restrict__ c,            // [256,384]
                                 float* __restrict__ out_t) {      // [256,384]
    const int b = blockIdx.x;
    const int i = threadIdx.x;   // 0..383
    const float* hr = hraw + (size_t)b * G4;

    float v[4];
    float s = 0.f, s2 = 0.f;
    #pragma unroll
    for (int q = 0; q < 4; q++) {
        v[q] = hr[i + q * HIDDEN];
        s += v[q];
        s2 = fmaf(v[q], v[q], s2);
    }
    float2 r2 = block_sum2<12>(s, s2);
    const float inv = 1.0f / (float)G4;
    float mu  = r2.x * inv;
    float var = fmaf(-mu, mu, r2.y * inv);
    float r   = rsqrtf(var + LN_EPS);

    float gate[4];
    #pragma unroll
    for (int q = 0; q < 4; q++) {
        int col = i + q * HIDDEN;
        float lnv = fmaf((v[q] - mu) * r, ghw[col], ghb[col]);
        gate[q] = xg_t[(size_t)b * G4 + col] + lnv + bias[col];
    }
    float ig = 1.f / (1.f + expf(-gate[0]));
    float fg = 1.f / (1.f + expf(-gate[1]));
    float og = 1.f / (1.f + expf(-gate[2]));
    float ug = tanhf(gate[3]);

    int idx = b * HIDDEN + i;
    float cn = fmaf(fg, c[idx], ig * ug);
    float hn = og * tanhf(cn);
    c[idx] = cn;
    h[idx] = hn;
    out_t[idx] = hn;
}

// ---------------------------------------------------------------------------
__global__ void copy_vec_kernel(const float* __restrict__ src,
                                float* __restrict__ dst, int n) {
    for (int i = blockIdx.x * blockDim.x + threadIdx.x; i < n;
         i += gridDim.x * blockDim.x)
        dst[i] = src[i];
}

// ---------------------------------------------------------------------------
extern "C" void kernel_launch(void* const* d_in, const int* in_sizes, int n_in,
                              void* d_out, int out_size) {
    const float* ent  = (const float*)d_in[0];
    const float* spa  = (const float*)d_in[1];
    const float* sca  = (const float*)d_in[2];
    const float* h0   = (const float*)d_in[3];
    const float* c0   = (const float*)d_in[4];
    const float* wx0  = (const float*)d_in[5];
    const float* wx1  = (const float*)d_in[6];
    const float* wx2  = (const float*)d_in[7];
    const float* wh   = (const float*)d_in[8];
    const float* bias = (const float*)d_in[9];
    const float* gxw  = (const float*)d_in[10];
    const float* gxb  = (const float*)d_in[11];
    const float* ghw  = (const float*)d_in[12];
    const float* ghb  = (const float*)d_in[13];
    float* out = (float*)d_out;

    float *x0, *x, *xg, *hraw, *h, *c;
    cudaGetSymbolAddress((void**)&x0,   g_x0);
    cudaGetSymbolAddress((void**)&x,    g_x);
    cudaGetSymbolAddress((void**)&xg,   g_xg);
    cudaGetSymbolAddress((void**)&hraw, g_hraw);
    cudaGetSymbolAddress((void**)&h,    g_h);
    cudaGetSymbolAddress((void**)&c,    g_c);

    concat_kernel<<<512, 256>>>((const float4*)ent, (const float4*)spa,
                                (const float4*)sca, (float4*)x0);

    const float* wx_l[3] = {wx0, wx1, wx2};
    const int    K_l[3]  = {DIN, HIDDEN, HIDDEN};
    const int BH = BATCH * HIDDEN;

    for (int l = 0; l < 3; l++) {
        const float* A = (l == 0) ? x0 : x;
        dim3 g1(G4 / 64, NROWS / 128);
        sgemm2_kernel<<<g1, 256>>>(A, wx_l[l], xg, NROWS, G4, K_l[l]);
        ln_rows_kernel<<<NROWS, 256>>>(xg, gxw + l * G4, gxb + l * G4);

        copy_vec_kernel<<<96, 512>>>(h0 + l * BH, h, BH);
        copy_vec_kernel<<<96, 512>>>(c0 + l * BH, c, BH);

        float* outbuf = (l == 2) ? (out + OUT_OUTPUT) : x;
        const float* wh_l = wh + (size_t)l * HIDDEN * G4;

        for (int t = 0; t < T_STEPS; t++) {
            dim3 g2(G4 / 64, BATCH / 32);
            sgemm2s_kernel<<<g2, 256>>>(h, wh_l, hraw);
            lstm_step_kernel<<<BATCH, HIDDEN>>>(
                hraw, xg + (size_t)t * BATCH * G4,
                bias + l * G4, ghw + l * G4, ghb + l * G4,
                h, c, outbuf + (size_t)t * BATCH * HIDDEN);
        }
        copy_vec_kernel<<<96, 512>>>(h, out + OUT_HN + l * BH, BH);
        copy_vec_kernel<<<96, 512>>>(c, out + OUT_CN + l * BH, BH);
    }
}